// round 5
// baseline (speedup 1.0000x reference)
#include <cuda_runtime.h>
#include <cstdint>

#define BB 2
#define NN 1024
#define CC 64
#define MI 8
#define TPB 256

#define ADD_F32X2(out, a, b) \
  asm("add.rn.f32x2 %0, %1, %2;" : "=l"(out) : "l"(a), "l"(b))
#define FMA_F32X2(out, a, b, c) \
  asm("fma.rn.f32x2 %0, %1, %2, %3;" : "=l"(out) : "l"(a), "l"(b), "l"(c))

// scratch: u[b,r,o] = sum_c x[b,r,c]*w1[o,c]  (512 KB) ; q[b,r] = 0.5*<w2,u_r>
__device__ __align__(16) float g_u[BB * NN * CC];
__device__ float g_q[BB * NN];

// ---------------- Phase 1: u = X @ W1^T, q = 0.5*u@w2 ----------------
// grid = B*N/4 blocks, 256 threads. Each block: 4 rows x 64 outputs.
__global__ __launch_bounds__(TPB) void uproj_kernel(
    const float* __restrict__ x, const float* __restrict__ w1,
    const float* __restrict__ w2) {
  __shared__ float wt[CC * 65];   // transposed w1, padded: wt[c*65+o]
  __shared__ float xs[4 * CC];
  __shared__ float qred[8];       // per-warp partial q sums
  int tid = threadIdx.x;

  for (int idx = tid; idx < CC * CC; idx += TPB) {
    int o = idx >> 6, c = idx & 63;
    wt[c * 65 + o] = w1[idx];
  }
  xs[tid] = x[blockIdx.x * (4 * CC) + tid];
  __syncthreads();

  int rr = tid >> 6, o = tid & 63;
  float acc = 0.f;
#pragma unroll
  for (int c = 0; c < CC; c++)
    acc = fmaf(xs[rr * CC + c], wt[c * 65 + o], acc);
  g_u[blockIdx.x * (4 * CC) + tid] = acc;

  // q = 0.5 * sum_o w2[o]*u[r,o]; row rr spans warps {2rr, 2rr+1}
  float v = acc * w2[o];
#pragma unroll
  for (int s = 16; s > 0; s >>= 1)
    v += __shfl_xor_sync(0xffffffffu, v, s);
  int warp = tid >> 5, lane = tid & 31;
  if (lane == 0) qred[warp] = v;
  __syncthreads();
  if (tid < 4)
    g_q[blockIdx.x * 4 + tid] = 0.5f * (qred[2 * tid] + qred[2 * tid + 1]);
}

// ---------------- Phase 2: scores + fused softmax ----------------
// relu(x) = (x+|x|)/2  =>
// score(b,i,j) = const_i + sum_o (0.5*w2[o])*|a_i[o]-u_j[o]| - q_j
// const_i cancels under softmax; a_i = u_i + b1; q_j = 0.5*<w2,u_j>.
// grid = B*N/MI = 256 blocks, 256 threads. Thread t owns j in {t+256*jt}.
__global__ __launch_bounds__(TPB, 2) void scores_kernel(
    const float* __restrict__ b1, const float* __restrict__ w2,
    float* __restrict__ out) {
  __shared__ __align__(16) float na_s[MI * CC];  // -(u_i + b1)
  __shared__ __align__(16) float w2_s[CC];       // 0.5*w2
  __shared__ float red[MI * 8];

  int tid = threadIdx.x;
  int b = blockIdx.x >> 7;
  int i0 = (blockIdx.x & 127) * MI;

  if (tid < CC) w2_s[tid] = 0.5f * w2[tid];
  for (int idx = tid; idx < MI * CC; idx += TPB) {
    int ii = idx >> 6, o = idx & 63;
    na_s[idx] = -(g_u[(b * NN + i0 + ii) * CC + o] + b1[o]);
  }
  __syncthreads();

  float sc[MI][4];
  const ulonglong2* ub = (const ulonglong2*)(g_u + (size_t)b * NN * CC);
  const ulonglong2* nap = (const ulonglong2*)na_s;   // 16 per i-row
  const ulonglong2* w2p = (const ulonglong2*)w2_s;
  const float* qb = g_q + (size_t)b * NN;
  const unsigned long long AM = 0x7FFFFFFF7FFFFFFFULL;

#pragma unroll
  for (int jt = 0; jt < 4; jt++) {
    int j = jt * TPB + tid;
    const ulonglong2* up = ub + (size_t)j * 16;
    unsigned long long acc0[MI], acc1[MI];
#pragma unroll
    for (int ii = 0; ii < MI; ii++) { acc0[ii] = 0ull; acc1[ii] = 0ull; }
#pragma unroll
    for (int k = 0; k < 16; k++) {       // 4 channels per k
      ulonglong2 uv = up[k];             // LDG.128 (L2-resident u_j)
      ulonglong2 wv = w2p[k];            // LDS.128 broadcast
#pragma unroll
      for (int ii = 0; ii < MI; ii++) {
        ulonglong2 na = nap[ii * 16 + k];   // LDS.128 broadcast
        unsigned long long d0, d1;
        ADD_F32X2(d0, uv.x, na.x);       // u_j - a_i  (|.| symmetric)
        ADD_F32X2(d1, uv.y, na.y);
        d0 &= AM;                        // packed abs (LOP3, alu pipe)
        d1 &= AM;
        FMA_F32X2(acc0[ii], wv.x, d0, acc0[ii]);
        FMA_F32X2(acc1[ii], wv.y, d1, acc1[ii]);
      }
    }
    float qj = qb[j];
#pragma unroll
    for (int ii = 0; ii < MI; ii++) {
      float2 a0 = *(float2*)&acc0[ii];
      float2 a1 = *(float2*)&acc1[ii];
      sc[ii][jt] = (a0.x + a1.x) + (a0.y + a1.y) - qj;
    }
  }

  // ---- fused softmax over j (1024 values per i-row across 256 threads) ----
  int warp = tid >> 5, lane = tid & 31;
  float rmax[MI], rinv[MI];

#pragma unroll
  for (int ii = 0; ii < MI; ii++) {
    float m = fmaxf(fmaxf(sc[ii][0], sc[ii][1]), fmaxf(sc[ii][2], sc[ii][3]));
#pragma unroll
    for (int s = 16; s > 0; s >>= 1)
      m = fmaxf(m, __shfl_xor_sync(0xffffffffu, m, s));
    if (lane == 0) red[ii * 8 + warp] = m;
  }
  __syncthreads();
#pragma unroll
  for (int ii = 0; ii < MI; ii++) {
    float m = red[ii * 8];
#pragma unroll
    for (int w = 1; w < 8; w++) m = fmaxf(m, red[ii * 8 + w]);
    rmax[ii] = m;
  }
  __syncthreads();   // max-reads complete before red reuse

#pragma unroll
  for (int ii = 0; ii < MI; ii++) {
    float s = 0.f;
#pragma unroll
    for (int jt = 0; jt < 4; jt++) {
      float e = __expf(sc[ii][jt] - rmax[ii]);
      sc[ii][jt] = e;
      s += e;
    }
#pragma unroll
    for (int sh = 16; sh > 0; sh >>= 1)
      s += __shfl_xor_sync(0xffffffffu, s, sh);
    if (lane == 0) red[ii * 8 + warp] = s;
  }
  __syncthreads();
#pragma unroll
  for (int ii = 0; ii < MI; ii++) {
    float s = red[ii * 8];
#pragma unroll
    for (int w = 1; w < 8; w++) s += red[ii * 8 + w];
    rinv[ii] = 1.0f / s;
  }

  // coalesced stores: out[b, i0+ii, jt*256 + tid]
  float* ob = out + ((size_t)b * NN + i0) * NN;
#pragma unroll
  for (int ii = 0; ii < MI; ii++)
#pragma unroll
    for (int jt = 0; jt < 4; jt++)
      ob[ii * NN + jt * TPB + tid] = sc[ii][jt] * rinv[ii];
}

extern "C" void kernel_launch(void* const* d_in, const int* in_sizes, int n_in,
                              void* d_out, int out_size) {
  const float* x  = (const float*)d_in[0];   // [2,1024,64] f32
  const float* w1 = (const float*)d_in[1];   // [64,64]
  const float* b1 = (const float*)d_in[2];   // [64]
  const float* w2 = (const float*)d_in[3];   // [64]
  // d_in[4] = b2 : additive scalar, cancels under softmax — unused
  float* out = (float*)d_out;                // [2,1024,1024] f32

  uproj_kernel<<<(BB * NN) / 4, TPB>>>(x, w1, w2);
  scores_kernel<<<(BB * NN) / MI, TPB>>>(b1, w2, out);
}

// round 6
// speedup vs baseline: 1.0033x; 1.0033x over previous
#include <cuda_runtime.h>
#include <cstdint>

#define BB 2
#define NN 1024
#define CC 64
#define MI 8
#define TPB 256

#define ADD_F32X2(out, a, b) \
  asm("add.rn.f32x2 %0, %1, %2;" : "=l"(out) : "l"(a), "l"(b))
#define FMA_F32X2(out, a, b, c) \
  asm("fma.rn.f32x2 %0, %1, %2, %3;" : "=l"(out) : "l"(a), "l"(b), "l"(c))

// scratch: u[b,r,o] = sum_c x[b,r,c]*w1[o,c]  (512 KB) ; q[b,r] = 0.5*<w2,u_r>
__device__ __align__(16) float g_u[BB * NN * CC];
__device__ float g_q[BB * NN];

// ---------------- Phase 1: u = X @ W1^T, q = 0.5*u@w2 ----------------
__global__ __launch_bounds__(TPB) void uproj_kernel(
    const float* __restrict__ x, const float* __restrict__ w1,
    const float* __restrict__ w2) {
  __shared__ float wt[CC * 65];
  __shared__ float xs[4 * CC];
  __shared__ float qred[8];
  int tid = threadIdx.x;

  for (int idx = tid; idx < CC * CC; idx += TPB) {
    int o = idx >> 6, c = idx & 63;
    wt[c * 65 + o] = w1[idx];
  }
  xs[tid] = x[blockIdx.x * (4 * CC) + tid];
  __syncthreads();

  int rr = tid >> 6, o = tid & 63;
  float acc = 0.f;
#pragma unroll
  for (int c = 0; c < CC; c++)
    acc = fmaf(xs[rr * CC + c], wt[c * 65 + o], acc);
  g_u[blockIdx.x * (4 * CC) + tid] = acc;

  float v = acc * w2[o];
#pragma unroll
  for (int s = 16; s > 0; s >>= 1)
    v += __shfl_xor_sync(0xffffffffu, v, s);
  int warp = tid >> 5, lane = tid & 31;
  if (lane == 0) qred[warp] = v;
  __syncthreads();
  if (tid < 4)
    g_q[blockIdx.x * 4 + tid] = 0.5f * (qred[2 * tid] + qred[2 * tid + 1]);
}

// ---------------- Phase 2: scores + fused softmax ----------------
// relu(x) = (x+|x|)/2  =>
// score(b,i,j) = const_i + sum_o (0.5*w2[o])*|a_i[o]-u_j[o]| - q_j
// const_i cancels under softmax; a_i = u_i + b1; q_j = 0.5*<w2,u_j>.
// Scores staged in SMEM (not registers!) to avoid local-memory spills:
// R5 showed regs=128 + 240MB DRAM traffic = sc[][] spilled to local.
__global__ __launch_bounds__(TPB, 2) void scores_kernel(
    const float* __restrict__ b1, const float* __restrict__ w2,
    float* __restrict__ out) {
  __shared__ __align__(16) float s_sc[MI * NN];  // 32 KB score staging
  __shared__ __align__(16) float na_s[MI * CC];  // -(u_i + b1)
  __shared__ __align__(16) float w2_s[CC];       // 0.5*w2
  __shared__ float red[MI * 8];

  int tid = threadIdx.x;
  int b = blockIdx.x >> 7;
  int i0 = (blockIdx.x & 127) * MI;

  if (tid < CC) w2_s[tid] = 0.5f * w2[tid];
  for (int idx = tid; idx < MI * CC; idx += TPB) {
    int ii = idx >> 6, o = idx & 63;
    na_s[idx] = -(g_u[(b * NN + i0 + ii) * CC + o] + b1[o]);
  }
  __syncthreads();

  const ulonglong2* ub = (const ulonglong2*)(g_u + (size_t)b * NN * CC);
  const ulonglong2* nap = (const ulonglong2*)na_s;   // 16 per i-row
  const ulonglong2* w2p = (const ulonglong2*)w2_s;
  const float* qb = g_q + (size_t)b * NN;
  const unsigned long long AM = 0x7FFFFFFF7FFFFFFFULL;

#pragma unroll
  for (int jt = 0; jt < 4; jt++) {
    int j = jt * TPB + tid;
    const ulonglong2* up = ub + (size_t)j * 16;
    unsigned long long acc0[MI], acc1[MI];
#pragma unroll
    for (int ii = 0; ii < MI; ii++) { acc0[ii] = 0ull; acc1[ii] = 0ull; }
#pragma unroll
    for (int k = 0; k < 16; k++) {       // 4 channels per k
      ulonglong2 uv = up[k];             // LDG.128 (L2-resident u_j)
      ulonglong2 wv = w2p[k];            // LDS.128 broadcast
#pragma unroll
      for (int ii = 0; ii < MI; ii++) {
        ulonglong2 na = nap[ii * 16 + k];   // LDS.128 broadcast
        unsigned long long d0, d1;
        ADD_F32X2(d0, uv.x, na.x);       // u_j - a_i  (|.| symmetric)
        ADD_F32X2(d1, uv.y, na.y);
        d0 &= AM;                        // packed abs (LOP3, alu pipe)
        d1 &= AM;
        FMA_F32X2(acc0[ii], wv.x, d0, acc0[ii]);
        FMA_F32X2(acc1[ii], wv.y, d1, acc1[ii]);
      }
    }
    float qj = qb[j];
#pragma unroll
    for (int ii = 0; ii < MI; ii++) {
      float2 a0 = *(float2*)&acc0[ii];
      float2 a1 = *(float2*)&acc1[ii];
      s_sc[ii * NN + j] = (a0.x + a1.x) + (a0.y + a1.y) - qj;
    }
  }
  __syncthreads();

  // ---- fused softmax over j (scores in SMEM) ----
  int warp = tid >> 5, lane = tid & 31;
  float rmax[MI], rinv[MI];

#pragma unroll
  for (int ii = 0; ii < MI; ii++) {
    float m = -1e30f;
#pragma unroll
    for (int jt = 0; jt < 4; jt++)
      m = fmaxf(m, s_sc[ii * NN + jt * TPB + tid]);
#pragma unroll
    for (int s = 16; s > 0; s >>= 1)
      m = fmaxf(m, __shfl_xor_sync(0xffffffffu, m, s));
    if (lane == 0) red[ii * 8 + warp] = m;
  }
  __syncthreads();
#pragma unroll
  for (int ii = 0; ii < MI; ii++) {
    float m = red[ii * 8];
#pragma unroll
    for (int w = 1; w < 8; w++) m = fmaxf(m, red[ii * 8 + w]);
    rmax[ii] = m;
  }
  __syncthreads();   // max-reads complete before red reuse

#pragma unroll
  for (int ii = 0; ii < MI; ii++) {
    float s = 0.f;
#pragma unroll
    for (int jt = 0; jt < 4; jt++) {
      int idx = ii * NN + jt * TPB + tid;
      float e = __expf(s_sc[idx] - rmax[ii]);
      s_sc[idx] = e;
      s += e;
    }
#pragma unroll
    for (int sh = 16; sh > 0; sh >>= 1)
      s += __shfl_xor_sync(0xffffffffu, s, sh);
    if (lane == 0) red[ii * 8 + warp] = s;
  }
  __syncthreads();
#pragma unroll
  for (int ii = 0; ii < MI; ii++) {
    float s = red[ii * 8];
#pragma unroll
    for (int w = 1; w < 8; w++) s += red[ii * 8 + w];
    rinv[ii] = 1.0f / s;
  }

  // coalesced stores: out[b, i0+ii, jt*256 + tid]
  float* ob = out + ((size_t)b * NN + i0) * NN;
#pragma unroll
  for (int ii = 0; ii < MI; ii++)
#pragma unroll
    for (int jt = 0; jt < 4; jt++)
      ob[ii * NN + jt * TPB + tid] = s_sc[ii * NN + jt * TPB + tid] * rinv[ii];
}

extern "C" void kernel_launch(void* const* d_in, const int* in_sizes, int n_in,
                              void* d_out, int out_size) {
  const float* x  = (const float*)d_in[0];   // [2,1024,64] f32
  const float* w1 = (const float*)d_in[1];   // [64,64]
  const float* b1 = (const float*)d_in[2];   // [64]
  const float* w2 = (const float*)d_in[3];   // [64]
  // d_in[4] = b2 : additive scalar, cancels under softmax — unused
  float* out = (float*)d_out;                // [2,1024,1024] f32

  uproj_kernel<<<(BB * NN) / 4, TPB>>>(x, w1, w2);
  scores_kernel<<<(BB * NN) / MI, TPB>>>(b1, w2, out);
}